// round 1
// baseline (speedup 1.0000x reference)
#include <cuda_runtime.h>

// ZapBench volume sampler: quadrilinear (trilinear spatial + linear temporal)
// frames: (T=3, Z=72, Y=512, X=1024) fp32, coords: (N, 4) fp32 [z, y, x, t]
// out: (N, 1) fp32

#define T_DIM 3
#define Z_DIM 72
#define Y_DIM 512
#define X_DIM 1024

__device__ __forceinline__ float trilerp_slice(
    const float* __restrict__ f, int t,
    int z0, int z1, int y0, int y1, int x0, int x1,
    float wz, float wy, float wx)
{
    const int tb = t * Z_DIM;
    const float* p00 = f + ((long)((tb + z0) * Y_DIM + y0) << 10);
    const float* p01 = f + ((long)((tb + z0) * Y_DIM + y1) << 10);
    const float* p10 = f + ((long)((tb + z1) * Y_DIM + y0) << 10);
    const float* p11 = f + ((long)((tb + z1) * Y_DIM + y1) << 10);

    // Issue all 8 loads before consuming — max MLP.
    float c000 = __ldg(p00 + x0);
    float c001 = __ldg(p00 + x1);
    float c010 = __ldg(p01 + x0);
    float c011 = __ldg(p01 + x1);
    float c100 = __ldg(p10 + x0);
    float c101 = __ldg(p10 + x1);
    float c110 = __ldg(p11 + x0);
    float c111 = __ldg(p11 + x1);

    float c00 = fmaf(wx, c001 - c000, c000);
    float c01 = fmaf(wx, c011 - c010, c010);
    float c10 = fmaf(wx, c101 - c100, c100);
    float c11 = fmaf(wx, c111 - c110, c110);
    float c0  = fmaf(wy, c01 - c00, c00);
    float c1  = fmaf(wy, c11 - c10, c10);
    return fmaf(wz, c1 - c0, c0);
}

__global__ void __launch_bounds__(256)
zapbench_sample_kernel(const float4* __restrict__ coords,
                       const float*  __restrict__ frames,
                       float*        __restrict__ out,
                       int n)
{
    int i = blockIdx.x * blockDim.x + threadIdx.x;
    if (i >= n) return;

    float4 c = coords[i];   // c.x = z_norm, c.y = y_norm, c.z = x_norm, c.w = t_norm

    // Temporal
    float t_abs = c.w * 3.0f;
    int t0 = (int)floorf(t_abs);
    t0 = max(0, min(t0, T_DIM - 2 + 1));     // clip to [0, 2]
    if (t0 > T_DIM - 1) t0 = T_DIM - 1;
    int t1 = min(t0 + 1, T_DIM - 1);
    float w = t_abs - (float)t0;

    // Spatial
    float sz = c.x * (float)(Z_DIM - 1);
    float sy = c.y * (float)(Y_DIM - 1);
    float sx = c.z * (float)(X_DIM - 1);

    int iz = (int)sz;  // inputs in [0,1) -> nonneg, trunc == floor
    int iy = (int)sy;
    int ix = (int)sx;

    float wz = sz - (float)iz;
    float wy = sy - (float)iy;
    float wx = sx - (float)ix;

    int z0 = max(0, min(iz, Z_DIM - 1));
    int y0 = max(0, min(iy, Y_DIM - 1));
    int x0 = max(0, min(ix, X_DIM - 1));
    int z1 = min(z0 + 1, Z_DIM - 1);
    int y1 = min(y0 + 1, Y_DIM - 1);
    int x1 = min(x0 + 1, X_DIM - 1);

    float val0 = trilerp_slice(frames, t0, z0, z1, y0, y1, x0, x1, wz, wy, wx);

    float result;
    if (t1 != t0) {
        float val1 = trilerp_slice(frames, t1, z0, z1, y0, y1, x0, x1, wz, wy, wx);
        result = fmaf(w, val1 - val0, val0);
    } else {
        result = val0;  // val1 == val0; lerp is identity
    }

    out[i] = result;
}

extern "C" void kernel_launch(void* const* d_in, const int* in_sizes, int n_in,
                              void* d_out, int out_size)
{
    const float4* coords = (const float4*)d_in[0];
    const float*  frames = (const float*)d_in[1];
    float* out = (float*)d_out;

    int n = in_sizes[0] / 4;   // coords is (N,4) floats
    int threads = 256;
    int blocks = (n + threads - 1) / threads;
    zapbench_sample_kernel<<<blocks, threads>>>(coords, frames, out, n);
}

// round 2
// speedup vs baseline: 1.0494x; 1.0494x over previous
#include <cuda_runtime.h>

// ZapBench volume sampler: quadrilinear (trilinear spatial + linear temporal)
// frames: (T=3, Z=72, Y=512, X=1024) fp32, coords: (N, 4) fp32 [z, y, x, t]
// out: (N, 1) fp32
//
// Strategy: counting-sort points into 1728 spatio-temporal bins so the main
// gather kernel processes spatially-clustered points -> volume reads hit L2
// instead of re-fetching from DRAM (measured 3.0 GB DRAM traffic on the
// unsorted version vs ~430 MB compulsory).

#define T_DIM 3
#define Z_DIM 72
#define Y_DIM 512
#define X_DIM 1024

#define NBINS (3 * 9 * 8 * 8)   // (t0, z/8, y/64, x/128) = 1728
#define CAP   (1 << 22)         // 4194304 points

__device__ unsigned int   g_hist[NBINS];
__device__ unsigned int   g_offsets[NBINS];
__device__ unsigned short g_bins[CAP];
__device__ unsigned int   g_sorted_idx[CAP];

__device__ __forceinline__ int compute_bin(float4 c)
{
    // c.x = z_norm, c.y = y_norm, c.z = x_norm, c.w = t_norm
    float t_abs = c.w * 3.0f;
    int t0 = min(max((int)t_abs, 0), 2);
    int zc = min(max((int)(c.x * (float)(Z_DIM - 1)), 0), Z_DIM - 1) >> 3;   // 0..8
    int yc = min(max((int)(c.y * (float)(Y_DIM - 1)), 0), Y_DIM - 1) >> 6;   // 0..7
    int xc = min(max((int)(c.z * (float)(X_DIM - 1)), 0), X_DIM - 1) >> 7;   // 0..7
    return ((t0 * 9 + zc) * 8 + yc) * 8 + xc;
}

__global__ void zero_hist_kernel()
{
    int i = blockIdx.x * blockDim.x + threadIdx.x;
    if (i < NBINS) g_hist[i] = 0;
}

__global__ void hist_kernel(const float4* __restrict__ coords, int n)
{
    __shared__ unsigned int sh[NBINS];
    for (int b = threadIdx.x; b < NBINS; b += blockDim.x) sh[b] = 0;
    __syncthreads();

    int stride = gridDim.x * blockDim.x;
    for (int i = blockIdx.x * blockDim.x + threadIdx.x; i < n; i += stride) {
        float4 c = coords[i];
        int bin = compute_bin(c);
        g_bins[i] = (unsigned short)bin;
        atomicAdd(&sh[bin], 1u);
    }
    __syncthreads();

    for (int b = threadIdx.x; b < NBINS; b += blockDim.x) {
        unsigned int v = sh[b];
        if (v) atomicAdd(&g_hist[b], v);
    }
}

// Exclusive scan over NBINS (<= 2048) entries, one CTA of 1024 threads.
__global__ void scan_kernel()
{
    __shared__ unsigned int buf[2][1024];
    int t = threadIdx.x;

    unsigned int h0 = (2 * t     < NBINS) ? g_hist[2 * t]     : 0u;
    unsigned int h1 = (2 * t + 1 < NBINS) ? g_hist[2 * t + 1] : 0u;
    unsigned int sum = h0 + h1;

    buf[0][t] = sum;
    __syncthreads();
    int src = 0;
    for (int d = 1; d < 1024; d <<= 1) {
        unsigned int v = buf[src][t];
        if (t >= d) v += buf[src][t - d];
        buf[src ^ 1][t] = v;
        __syncthreads();
        src ^= 1;
    }
    unsigned int inclusive = buf[src][t];
    unsigned int base = inclusive - sum;   // exclusive

    if (2 * t     < NBINS) g_offsets[2 * t]     = base;
    if (2 * t + 1 < NBINS) g_offsets[2 * t + 1] = base + h0;
}

__global__ void scatter_kernel(int n)
{
    int stride = gridDim.x * blockDim.x;
    for (int i = blockIdx.x * blockDim.x + threadIdx.x; i < n; i += stride) {
        int bin = g_bins[i];
        unsigned int pos = atomicAdd(&g_offsets[bin], 1u);
        g_sorted_idx[pos] = (unsigned int)i;
    }
}

__device__ __forceinline__ float trilerp_slice(
    const float* __restrict__ f, int t,
    int z0, int z1, int y0, int y1, int x0, int x1,
    float wz, float wy, float wx)
{
    const int tb = t * Z_DIM;
    const float* p00 = f + ((long)((tb + z0) * Y_DIM + y0) << 10);
    const float* p01 = f + ((long)((tb + z0) * Y_DIM + y1) << 10);
    const float* p10 = f + ((long)((tb + z1) * Y_DIM + y0) << 10);
    const float* p11 = f + ((long)((tb + z1) * Y_DIM + y1) << 10);

    float c000 = __ldg(p00 + x0);
    float c001 = __ldg(p00 + x1);
    float c010 = __ldg(p01 + x0);
    float c011 = __ldg(p01 + x1);
    float c100 = __ldg(p10 + x0);
    float c101 = __ldg(p10 + x1);
    float c110 = __ldg(p11 + x0);
    float c111 = __ldg(p11 + x1);

    float c00 = fmaf(wx, c001 - c000, c000);
    float c01 = fmaf(wx, c011 - c010, c010);
    float c10 = fmaf(wx, c101 - c100, c100);
    float c11 = fmaf(wx, c111 - c110, c110);
    float c0  = fmaf(wy, c01 - c00, c00);
    float c1  = fmaf(wy, c11 - c10, c10);
    return fmaf(wz, c1 - c0, c0);
}

__device__ __forceinline__ float sample_point(
    const float4 c, const float* __restrict__ frames)
{
    float t_abs = c.w * 3.0f;
    int t0 = min(max((int)t_abs, 0), 2);
    int t1 = min(t0 + 1, T_DIM - 1);
    float w = t_abs - (float)t0;

    float sz = c.x * (float)(Z_DIM - 1);
    float sy = c.y * (float)(Y_DIM - 1);
    float sx = c.z * (float)(X_DIM - 1);

    int iz = (int)sz;   // inputs in [0,1): trunc == floor
    int iy = (int)sy;
    int ix = (int)sx;

    float wz = sz - (float)iz;
    float wy = sy - (float)iy;
    float wx = sx - (float)ix;

    int z0 = max(0, min(iz, Z_DIM - 1));
    int y0 = max(0, min(iy, Y_DIM - 1));
    int x0 = max(0, min(ix, X_DIM - 1));
    int z1 = min(z0 + 1, Z_DIM - 1);
    int y1 = min(y0 + 1, Y_DIM - 1);
    int x1 = min(x0 + 1, X_DIM - 1);

    float val0 = trilerp_slice(frames, t0, z0, z1, y0, y1, x0, x1, wz, wy, wx);

    if (t1 != t0) {
        float val1 = trilerp_slice(frames, t1, z0, z1, y0, y1, x0, x1, wz, wy, wx);
        return fmaf(w, val1 - val0, val0);
    }
    return val0;
}

__global__ void __launch_bounds__(256)
sample_sorted_kernel(const float4* __restrict__ coords,
                     const float*  __restrict__ frames,
                     float*        __restrict__ out,
                     int n)
{
    int j = blockIdx.x * blockDim.x + threadIdx.x;
    if (j >= n) return;

    unsigned int i = __ldg(&g_sorted_idx[j]);
    float4 c = __ldg(&coords[i]);
    out[i] = sample_point(c, frames);
}

__global__ void __launch_bounds__(256)
sample_direct_kernel(const float4* __restrict__ coords,
                     const float*  __restrict__ frames,
                     float*        __restrict__ out,
                     int n)
{
    int i = blockIdx.x * blockDim.x + threadIdx.x;
    if (i >= n) return;
    float4 c = __ldg(&coords[i]);
    out[i] = sample_point(c, frames);
}

extern "C" void kernel_launch(void* const* d_in, const int* in_sizes, int n_in,
                              void* d_out, int out_size)
{
    const float4* coords = (const float4*)d_in[0];
    const float*  frames = (const float*)d_in[1];
    float* out = (float*)d_out;

    int n = in_sizes[0] / 4;   // coords is (N,4) floats
    int threads = 256;
    int blocks = (n + threads - 1) / threads;

    if (n > CAP) {
        // scratch too small (shouldn't happen for this problem) — direct path
        sample_direct_kernel<<<blocks, threads>>>(coords, frames, out, n);
        return;
    }

    zero_hist_kernel<<<(NBINS + 255) / 256, 256>>>();
    hist_kernel<<<2048, 256>>>(coords, n);
    scan_kernel<<<1, 1024>>>();
    scatter_kernel<<<2048, 256>>>(n);
    sample_sorted_kernel<<<blocks, threads>>>(coords, frames, out, n);
}

// round 3
// speedup vs baseline: 1.6280x; 1.5513x over previous
#include <cuda_runtime.h>

// ZapBench volume sampler: quadrilinear (trilinear spatial + linear temporal)
// frames: (T=3, Z=72, Y=512, X=1024) fp32, coords: (N, 4) fp32 [z, y, x, t]
// out: (N, 1) fp32
//
// Pipeline: counting-sort point indices into 1728 spatio-temporal bins so the
// gather kernel sees spatially-clustered points (volume reads become L2 hits).
// R2 lesson: naive per-point global atomic scatter cost 230us; replaced with
// CTA-aggregated scatter (smem histogram + one global atomic per CTA-bin).

#define T_DIM 3
#define Z_DIM 72
#define Y_DIM 512
#define X_DIM 1024

#define NBINS (3 * 9 * 8 * 8)   // (t0, z/8, y/64, x/128) = 1728
#define CAP   (1 << 22)         // 4194304 points
#define SCAT_BLOCKS 512
#define SCAT_THREADS 256

__device__ unsigned int   g_hist[NBINS];
__device__ unsigned int   g_offsets[NBINS];
__device__ unsigned short g_bins[CAP];
__device__ unsigned int   g_sorted_idx[CAP];

__device__ __forceinline__ int compute_bin(float4 c)
{
    // c.x = z_norm, c.y = y_norm, c.z = x_norm, c.w = t_norm
    float t_abs = c.w * 3.0f;
    int t0 = min(max((int)t_abs, 0), 2);
    int zc = min(max((int)(c.x * (float)(Z_DIM - 1)), 0), Z_DIM - 1) >> 3;   // 0..8
    int yc = min(max((int)(c.y * (float)(Y_DIM - 1)), 0), Y_DIM - 1) >> 6;   // 0..7
    int xc = min(max((int)(c.z * (float)(X_DIM - 1)), 0), X_DIM - 1) >> 7;   // 0..7
    return ((t0 * 9 + zc) * 8 + yc) * 8 + xc;
}

__global__ void zero_hist_kernel()
{
    int i = blockIdx.x * blockDim.x + threadIdx.x;
    if (i < NBINS) g_hist[i] = 0;
}

__global__ void hist_kernel(const float4* __restrict__ coords, int n)
{
    __shared__ unsigned int sh[NBINS];
    for (int b = threadIdx.x; b < NBINS; b += blockDim.x) sh[b] = 0;
    __syncthreads();

    int stride = gridDim.x * blockDim.x;
    for (int i = blockIdx.x * blockDim.x + threadIdx.x; i < n; i += stride) {
        float4 c = coords[i];
        int bin = compute_bin(c);
        g_bins[i] = (unsigned short)bin;
        atomicAdd(&sh[bin], 1u);
    }
    __syncthreads();

    for (int b = threadIdx.x; b < NBINS; b += blockDim.x) {
        unsigned int v = sh[b];
        if (v) atomicAdd(&g_hist[b], v);
    }
}

// Exclusive scan over NBINS (<= 2048) entries, one CTA of 1024 threads.
__global__ void scan_kernel()
{
    __shared__ unsigned int buf[2][1024];
    int t = threadIdx.x;

    unsigned int h0 = (2 * t     < NBINS) ? g_hist[2 * t]     : 0u;
    unsigned int h1 = (2 * t + 1 < NBINS) ? g_hist[2 * t + 1] : 0u;
    unsigned int sum = h0 + h1;

    buf[0][t] = sum;
    __syncthreads();
    int src = 0;
    for (int d = 1; d < 1024; d <<= 1) {
        unsigned int v = buf[src][t];
        if (t >= d) v += buf[src][t - d];
        buf[src ^ 1][t] = v;
        __syncthreads();
        src ^= 1;
    }
    unsigned int inclusive = buf[src][t];
    unsigned int base = inclusive - sum;   // exclusive

    if (2 * t     < NBINS) g_offsets[2 * t]     = base;
    if (2 * t + 1 < NBINS) g_offsets[2 * t + 1] = base + h0;
}

// CTA-aggregated scatter: each block owns a contiguous chunk of points.
// Phase A: smem histogram of the chunk.
// Phase B: one atomicAdd per touched bin reserves a contiguous range.
// Phase C: place indices via smem counters (low-contention smem atomics).
__global__ void __launch_bounds__(SCAT_THREADS)
scatter_kernel(int n)
{
    __shared__ unsigned int s_cnt[NBINS];
    __shared__ unsigned int s_base[NBINS];

    int chunk = (n + gridDim.x - 1) / gridDim.x;
    int start = blockIdx.x * chunk;
    int end   = min(start + chunk, n);
    if (start >= end) return;

    for (int b = threadIdx.x; b < NBINS; b += blockDim.x) s_cnt[b] = 0;
    __syncthreads();

    // Phase A
    for (int i = start + threadIdx.x; i < end; i += blockDim.x) {
        atomicAdd(&s_cnt[g_bins[i]], 1u);
    }
    __syncthreads();

    // Phase B
    for (int b = threadIdx.x; b < NBINS; b += blockDim.x) {
        unsigned int cnt = s_cnt[b];
        s_base[b] = cnt ? atomicAdd(&g_offsets[b], cnt) : 0u;
        s_cnt[b] = 0;
    }
    __syncthreads();

    // Phase C
    for (int i = start + threadIdx.x; i < end; i += blockDim.x) {
        int bin = g_bins[i];
        unsigned int pos = s_base[bin] + atomicAdd(&s_cnt[bin], 1u);
        g_sorted_idx[pos] = (unsigned int)i;
    }
}

__device__ __forceinline__ float trilerp_slice(
    const float* __restrict__ f, int t,
    int z0, int z1, int y0, int y1, int x0, int x1,
    float wz, float wy, float wx)
{
    const int tb = t * Z_DIM;
    const float* p00 = f + ((long)((tb + z0) * Y_DIM + y0) << 10);
    const float* p01 = f + ((long)((tb + z0) * Y_DIM + y1) << 10);
    const float* p10 = f + ((long)((tb + z1) * Y_DIM + y0) << 10);
    const float* p11 = f + ((long)((tb + z1) * Y_DIM + y1) << 10);

    float c000 = __ldg(p00 + x0);
    float c001 = __ldg(p00 + x1);
    float c010 = __ldg(p01 + x0);
    float c011 = __ldg(p01 + x1);
    float c100 = __ldg(p10 + x0);
    float c101 = __ldg(p10 + x1);
    float c110 = __ldg(p11 + x0);
    float c111 = __ldg(p11 + x1);

    float c00 = fmaf(wx, c001 - c000, c000);
    float c01 = fmaf(wx, c011 - c010, c010);
    float c10 = fmaf(wx, c101 - c100, c100);
    float c11 = fmaf(wx, c111 - c110, c110);
    float c0  = fmaf(wy, c01 - c00, c00);
    float c1  = fmaf(wy, c11 - c10, c10);
    return fmaf(wz, c1 - c0, c0);
}

__device__ __forceinline__ float sample_point(
    const float4 c, const float* __restrict__ frames)
{
    float t_abs = c.w * 3.0f;
    int t0 = min(max((int)t_abs, 0), 2);
    int t1 = min(t0 + 1, T_DIM - 1);
    float w = t_abs - (float)t0;

    float sz = c.x * (float)(Z_DIM - 1);
    float sy = c.y * (float)(Y_DIM - 1);
    float sx = c.z * (float)(X_DIM - 1);

    int iz = (int)sz;   // inputs in [0,1): trunc == floor
    int iy = (int)sy;
    int ix = (int)sx;

    float wz = sz - (float)iz;
    float wy = sy - (float)iy;
    float wx = sx - (float)ix;

    int z0 = max(0, min(iz, Z_DIM - 1));
    int y0 = max(0, min(iy, Y_DIM - 1));
    int x0 = max(0, min(ix, X_DIM - 1));
    int z1 = min(z0 + 1, Z_DIM - 1);
    int y1 = min(y0 + 1, Y_DIM - 1);
    int x1 = min(x0 + 1, X_DIM - 1);

    float val0 = trilerp_slice(frames, t0, z0, z1, y0, y1, x0, x1, wz, wy, wx);

    if (t1 != t0) {
        float val1 = trilerp_slice(frames, t1, z0, z1, y0, y1, x0, x1, wz, wy, wx);
        return fmaf(w, val1 - val0, val0);
    }
    return val0;
}

__global__ void __launch_bounds__(256)
sample_sorted_kernel(const float4* __restrict__ coords,
                     const float*  __restrict__ frames,
                     float*        __restrict__ out,
                     int n)
{
    int j = blockIdx.x * blockDim.x + threadIdx.x;
    if (j >= n) return;

    unsigned int i = __ldg(&g_sorted_idx[j]);
    float4 c = __ldg(&coords[i]);
    out[i] = sample_point(c, frames);
}

__global__ void __launch_bounds__(256)
sample_direct_kernel(const float4* __restrict__ coords,
                     const float*  __restrict__ frames,
                     float*        __restrict__ out,
                     int n)
{
    int i = blockIdx.x * blockDim.x + threadIdx.x;
    if (i >= n) return;
    float4 c = __ldg(&coords[i]);
    out[i] = sample_point(c, frames);
}

extern "C" void kernel_launch(void* const* d_in, const int* in_sizes, int n_in,
                              void* d_out, int out_size)
{
    const float4* coords = (const float4*)d_in[0];
    const float*  frames = (const float*)d_in[1];
    float* out = (float*)d_out;

    int n = in_sizes[0] / 4;   // coords is (N,4) floats
    int threads = 256;
    int blocks = (n + threads - 1) / threads;

    if (n > CAP) {
        sample_direct_kernel<<<blocks, threads>>>(coords, frames, out, n);
        return;
    }

    zero_hist_kernel<<<(NBINS + 255) / 256, 256>>>();
    hist_kernel<<<2048, 256>>>(coords, n);
    scan_kernel<<<1, 1024>>>();
    scatter_kernel<<<SCAT_BLOCKS, SCAT_THREADS>>>(n);
    sample_sorted_kernel<<<blocks, threads>>>(coords, frames, out, n);
}

// round 4
// speedup vs baseline: 1.8760x; 1.1523x over previous
#include <cuda_runtime.h>

// ZapBench volume sampler: quadrilinear (trilinear spatial + linear temporal)
// frames: (T=3, Z=72, Y=512, X=1024) fp32, coords: (N, 4) fp32 [z, y, x, t]
// out: (N, 1) fp32
//
// Pipeline: atomic-free multi-block counting sort into 1728 bins
// (t0 INNERMOST so all three time-groups of a spatial region are adjacent in
// sorted order -> each frame slice streamed from DRAM ~once), then a gather
// kernel that processes points in bin order so volume reads hit L2.

#define T_DIM 3
#define Z_DIM 72
#define Y_DIM 512
#define X_DIM 1024

#define NBINS (9 * 8 * 8 * 3)   // (z/8, y/64, x/128) spatial, t0 innermost = 1728
#define CAP   (1 << 22)         // 4194304 points
#define NCTA  512               // chunks for hist/scatter
#define CHUNK_THREADS 256

__device__ unsigned int   g_hist2d[NBINS * NCTA];  // [bin][cta], 3.5 MB
__device__ unsigned int   g_bintotal[NBINS];
__device__ unsigned int   g_binbase[NBINS];
__device__ unsigned short g_bins[CAP];
__device__ unsigned int   g_sorted_idx[CAP];

__device__ __forceinline__ int compute_bin(float4 c)
{
    // c.x = z_norm, c.y = y_norm, c.z = x_norm, c.w = t_norm
    float t_abs = c.w * 3.0f;
    int t0 = min(max((int)t_abs, 0), 2);
    int zc = min(max((int)(c.x * (float)(Z_DIM - 1)), 0), Z_DIM - 1) >> 3;   // 0..8
    int yc = min(max((int)(c.y * (float)(Y_DIM - 1)), 0), Y_DIM - 1) >> 6;   // 0..7
    int xc = min(max((int)(c.z * (float)(X_DIM - 1)), 0), X_DIM - 1) >> 7;   // 0..7
    return (((zc * 8 + yc) * 8 + xc) * 3) + t0;   // t innermost
}

// Per-chunk histogram. CTA b owns points [b*chunk, (b+1)*chunk).
// Writes its counts to g_hist2d[bin * NCTA + cta] (every slot written, incl 0).
__global__ void __launch_bounds__(CHUNK_THREADS)
hist_kernel(const float4* __restrict__ coords, int n, int chunk)
{
    __shared__ unsigned int s_cnt[NBINS];
    for (int b = threadIdx.x; b < NBINS; b += blockDim.x) s_cnt[b] = 0;
    __syncthreads();

    int start = blockIdx.x * chunk;
    int end   = min(start + chunk, n);

    for (int i = start + threadIdx.x; i < end; i += blockDim.x) {
        float4 c = __ldg(&coords[i]);
        int bin = compute_bin(c);
        g_bins[i] = (unsigned short)bin;
        atomicAdd(&s_cnt[bin], 1u);
    }
    __syncthreads();

    unsigned int cta = blockIdx.x;
    for (int b = threadIdx.x; b < NBINS; b += blockDim.x) {
        g_hist2d[(unsigned int)b * NCTA + cta] = s_cnt[b];
    }
}

// Scan pass 1: one CTA per bin. Exclusive scan of the bin's NCTA counts
// (contiguous in memory), write prefix back in place, emit bin total.
__global__ void __launch_bounds__(NCTA)
scan1_kernel()
{
    __shared__ unsigned int buf[2][NCTA];
    int b = blockIdx.x;
    int t = threadIdx.x;

    unsigned int v = g_hist2d[(unsigned int)b * NCTA + t];
    buf[0][t] = v;
    __syncthreads();

    int src = 0;
    for (int d = 1; d < NCTA; d <<= 1) {
        unsigned int x = buf[src][t];
        if (t >= d) x += buf[src][t - d];
        buf[src ^ 1][t] = x;
        __syncthreads();
        src ^= 1;
    }
    unsigned int inclusive = buf[src][t];
    g_hist2d[(unsigned int)b * NCTA + t] = inclusive - v;   // exclusive within bin
    if (t == NCTA - 1) g_bintotal[b] = inclusive;
}

// Scan pass 2: exclusive scan over NBINS (<=2048) bin totals, 1 CTA.
__global__ void __launch_bounds__(1024)
scan2_kernel()
{
    __shared__ unsigned int buf[2][1024];
    int t = threadIdx.x;

    unsigned int h0 = (2 * t     < NBINS) ? g_bintotal[2 * t]     : 0u;
    unsigned int h1 = (2 * t + 1 < NBINS) ? g_bintotal[2 * t + 1] : 0u;
    unsigned int sum = h0 + h1;

    buf[0][t] = sum;
    __syncthreads();
    int src = 0;
    for (int d = 1; d < 1024; d <<= 1) {
        unsigned int v = buf[src][t];
        if (t >= d) v += buf[src][t - d];
        buf[src ^ 1][t] = v;
        __syncthreads();
        src ^= 1;
    }
    unsigned int inclusive = buf[src][t];
    unsigned int base = inclusive - sum;   // exclusive

    if (2 * t     < NBINS) g_binbase[2 * t]     = base;
    if (2 * t + 1 < NBINS) g_binbase[2 * t + 1] = base + h0;
}

// Scatter: CTA c places its chunk's indices at exact precomputed positions.
// No global atomics; only low-contention smem counters.
__global__ void __launch_bounds__(CHUNK_THREADS)
scatter_kernel(int n, int chunk)
{
    __shared__ unsigned int s_base[NBINS];
    __shared__ unsigned int s_cnt[NBINS];

    unsigned int cta = blockIdx.x;
    for (int b = threadIdx.x; b < NBINS; b += blockDim.x) {
        s_base[b] = g_binbase[b] + g_hist2d[(unsigned int)b * NCTA + cta];
        s_cnt[b]  = 0;
    }
    __syncthreads();

    int start = blockIdx.x * chunk;
    int end   = min(start + chunk, n);

    for (int i = start + threadIdx.x; i < end; i += blockDim.x) {
        int bin = g_bins[i];
        unsigned int pos = s_base[bin] + atomicAdd(&s_cnt[bin], 1u);
        g_sorted_idx[pos] = (unsigned int)i;
    }
}

__device__ __forceinline__ float trilerp_slice(
    const float* __restrict__ f, int t,
    int z0, int z1, int y0, int y1, int x0, int x1,
    float wz, float wy, float wx)
{
    const int tb = t * Z_DIM;
    const float* p00 = f + ((long)((tb + z0) * Y_DIM + y0) << 10);
    const float* p01 = f + ((long)((tb + z0) * Y_DIM + y1) << 10);
    const float* p10 = f + ((long)((tb + z1) * Y_DIM + y0) << 10);
    const float* p11 = f + ((long)((tb + z1) * Y_DIM + y1) << 10);

    float c000 = __ldg(p00 + x0);
    float c001 = __ldg(p00 + x1);
    float c010 = __ldg(p01 + x0);
    float c011 = __ldg(p01 + x1);
    float c100 = __ldg(p10 + x0);
    float c101 = __ldg(p10 + x1);
    float c110 = __ldg(p11 + x0);
    float c111 = __ldg(p11 + x1);

    float c00 = fmaf(wx, c001 - c000, c000);
    float c01 = fmaf(wx, c011 - c010, c010);
    float c10 = fmaf(wx, c101 - c100, c100);
    float c11 = fmaf(wx, c111 - c110, c110);
    float c0  = fmaf(wy, c01 - c00, c00);
    float c1  = fmaf(wy, c11 - c10, c10);
    return fmaf(wz, c1 - c0, c0);
}

__device__ __forceinline__ float sample_point(
    const float4 c, const float* __restrict__ frames)
{
    float t_abs = c.w * 3.0f;
    int t0 = min(max((int)t_abs, 0), 2);
    int t1 = min(t0 + 1, T_DIM - 1);
    float w = t_abs - (float)t0;

    float sz = c.x * (float)(Z_DIM - 1);
    float sy = c.y * (float)(Y_DIM - 1);
    float sx = c.z * (float)(X_DIM - 1);

    int iz = (int)sz;   // inputs in [0,1): trunc == floor
    int iy = (int)sy;
    int ix = (int)sx;

    float wz = sz - (float)iz;
    float wy = sy - (float)iy;
    float wx = sx - (float)ix;

    int z0 = max(0, min(iz, Z_DIM - 1));
    int y0 = max(0, min(iy, Y_DIM - 1));
    int x0 = max(0, min(ix, X_DIM - 1));
    int z1 = min(z0 + 1, Z_DIM - 1);
    int y1 = min(y0 + 1, Y_DIM - 1);
    int x1 = min(x0 + 1, X_DIM - 1);

    float val0 = trilerp_slice(frames, t0, z0, z1, y0, y1, x0, x1, wz, wy, wx);

    if (t1 != t0) {
        float val1 = trilerp_slice(frames, t1, z0, z1, y0, y1, x0, x1, wz, wy, wx);
        return fmaf(w, val1 - val0, val0);
    }
    return val0;
}

__global__ void __launch_bounds__(256)
sample_sorted_kernel(const float4* __restrict__ coords,
                     const float*  __restrict__ frames,
                     float*        __restrict__ out,
                     int n)
{
    int j = blockIdx.x * blockDim.x + threadIdx.x;
    if (j >= n) return;

    unsigned int i = __ldg(&g_sorted_idx[j]);
    float4 c = __ldg(&coords[i]);
    out[i] = sample_point(c, frames);
}

__global__ void __launch_bounds__(256)
sample_direct_kernel(const float4* __restrict__ coords,
                     const float*  __restrict__ frames,
                     float*        __restrict__ out,
                     int n)
{
    int i = blockIdx.x * blockDim.x + threadIdx.x;
    if (i >= n) return;
    float4 c = __ldg(&coords[i]);
    out[i] = sample_point(c, frames);
}

extern "C" void kernel_launch(void* const* d_in, const int* in_sizes, int n_in,
                              void* d_out, int out_size)
{
    const float4* coords = (const float4*)d_in[0];
    const float*  frames = (const float*)d_in[1];
    float* out = (float*)d_out;

    int n = in_sizes[0] / 4;   // coords is (N,4) floats
    int threads = 256;
    int blocks = (n + threads - 1) / threads;

    if (n > CAP) {
        sample_direct_kernel<<<blocks, threads>>>(coords, frames, out, n);
        return;
    }

    int chunk = (n + NCTA - 1) / NCTA;

    hist_kernel<<<NCTA, CHUNK_THREADS>>>(coords, n, chunk);
    scan1_kernel<<<NBINS, NCTA>>>();
    scan2_kernel<<<1, 1024>>>();
    scatter_kernel<<<NCTA, CHUNK_THREADS>>>(n, chunk);
    sample_sorted_kernel<<<blocks, threads>>>(coords, frames, out, n);
}